// round 1
// baseline (speedup 1.0000x reference)
#include <cuda_runtime.h>
#include <cstdint>
#include <cstddef>

// ---------------- static scratch (no cudaMalloc allowed) ----------------
// layouts:
//   g_h   [NH=4][16384][256]  LN'd head features
//   g_tmp [4][16384][256]     pre-LN fc output, then reused for g = h@adjw
//   g_S   [4][16][1024][1024] attention logits S = g @ h^T
//   g_out [4][16384][256]     per-head attention output
//   g_esrc/g_edst [4][16384]
//   g_mean [4][16][256]
__device__ float g_h[4 * 16384 * 256];
__device__ float g_tmp[4 * 16384 * 256];
__device__ float g_S[4 * 16 * 1024 * 1024];
__device__ float g_out[4 * 16384 * 256];
__device__ float g_esrc[4 * 16384];
__device__ float g_edst[4 * 16384];
__device__ float g_mean[4 * 16 * 256];

// ---------------- generic 128x128x8 fp32 GEMM, C = A@B (+bias) ----------------
// A: M x K row-major, B: K x N row-major, C: M x N row-major.
// blockIdx.z = batch; per-batch pointer strides passed explicitly.
// All dims divisible by tile sizes in this problem (no bounds checks).
__global__ void __launch_bounds__(256, 2)
sgemm_nn(const float* __restrict__ Ab, const float* __restrict__ Bb,
         float* __restrict__ Cb, const float* __restrict__ biasb,
         int M, int N, int K,
         size_t sA, size_t sB, size_t sC, size_t sBias)
{
    const float* A = Ab + (size_t)blockIdx.z * sA;
    const float* B = Bb + (size_t)blockIdx.z * sB;
    float* C = Cb + (size_t)blockIdx.z * sC;
    const float* bias = biasb ? biasb + (size_t)blockIdx.z * sBias : nullptr;

    __shared__ float As[8][128];
    __shared__ float Bs[8][128];

    const int tid = threadIdx.x;
    const int row0 = blockIdx.y * 128;
    const int col0 = blockIdx.x * 128;

    const int arow = tid >> 1;            // 0..127
    const int acol = (tid & 1) * 4;       // 0 or 4
    const int brow = tid >> 5;            // 0..7
    const int bcol = (tid & 31) * 4;      // 0..124

    const int ty = tid >> 4, tx = tid & 15;
    const int r0 = ty * 8, c0 = tx * 8;

    float acc[8][8];
#pragma unroll
    for (int i = 0; i < 8; i++)
#pragma unroll
        for (int j = 0; j < 8; j++) acc[i][j] = 0.f;

    for (int k0 = 0; k0 < K; k0 += 8) {
        float4 av = *(const float4*)(A + (size_t)(row0 + arow) * K + k0 + acol);
        float4 bv = *(const float4*)(B + (size_t)(k0 + brow) * N + col0 + bcol);
        __syncthreads();
        As[acol + 0][arow] = av.x; As[acol + 1][arow] = av.y;
        As[acol + 2][arow] = av.z; As[acol + 3][arow] = av.w;
        *(float4*)&Bs[brow][bcol] = bv;
        __syncthreads();
#pragma unroll
        for (int kk = 0; kk < 8; kk++) {
            float a[8], b[8];
            *(float4*)(a)     = *(const float4*)&As[kk][r0];
            *(float4*)(a + 4) = *(const float4*)&As[kk][r0 + 4];
            *(float4*)(b)     = *(const float4*)&Bs[kk][c0];
            *(float4*)(b + 4) = *(const float4*)&Bs[kk][c0 + 4];
#pragma unroll
            for (int i = 0; i < 8; i++)
#pragma unroll
                for (int j = 0; j < 8; j++) acc[i][j] += a[i] * b[j];
        }
    }

#pragma unroll
    for (int i = 0; i < 8; i++) {
        size_t cr = (size_t)(row0 + r0 + i) * N + col0 + c0;
#pragma unroll
        for (int j = 0; j < 8; j++) {
            float v = acc[i][j];
            if (bias) v += bias[col0 + c0 + j];
            C[cr + j] = v;
        }
    }
}

// ---------------- C = A @ B^T, B stored N x K row-major ----------------
__global__ void __launch_bounds__(256, 2)
sgemm_nt(const float* __restrict__ Ab, const float* __restrict__ Bb,
         float* __restrict__ Cb,
         int M, int N, int K,
         size_t sA, size_t sB, size_t sC)
{
    const float* A = Ab + (size_t)blockIdx.z * sA;
    const float* B = Bb + (size_t)blockIdx.z * sB;
    float* C = Cb + (size_t)blockIdx.z * sC;

    __shared__ float As[8][128];
    __shared__ float Bs[8][128];

    const int tid = threadIdx.x;
    const int row0 = blockIdx.y * 128;
    const int col0 = blockIdx.x * 128;

    const int arow = tid >> 1;
    const int acol = (tid & 1) * 4;

    const int ty = tid >> 4, tx = tid & 15;
    const int r0 = ty * 8, c0 = tx * 8;

    float acc[8][8];
#pragma unroll
    for (int i = 0; i < 8; i++)
#pragma unroll
        for (int j = 0; j < 8; j++) acc[i][j] = 0.f;

    for (int k0 = 0; k0 < K; k0 += 8) {
        float4 av = *(const float4*)(A + (size_t)(row0 + arow) * K + k0 + acol);
        float4 bv = *(const float4*)(B + (size_t)(col0 + arow) * K + k0 + acol);
        __syncthreads();
        As[acol + 0][arow] = av.x; As[acol + 1][arow] = av.y;
        As[acol + 2][arow] = av.z; As[acol + 3][arow] = av.w;
        Bs[acol + 0][arow] = bv.x; Bs[acol + 1][arow] = bv.y;
        Bs[acol + 2][arow] = bv.z; Bs[acol + 3][arow] = bv.w;
        __syncthreads();
#pragma unroll
        for (int kk = 0; kk < 8; kk++) {
            float a[8], b[8];
            *(float4*)(a)     = *(const float4*)&As[kk][r0];
            *(float4*)(a + 4) = *(const float4*)&As[kk][r0 + 4];
            *(float4*)(b)     = *(const float4*)&Bs[kk][c0];
            *(float4*)(b + 4) = *(const float4*)&Bs[kk][c0 + 4];
#pragma unroll
            for (int i = 0; i < 8; i++)
#pragma unroll
                for (int j = 0; j < 8; j++) acc[i][j] += a[i] * b[j];
        }
    }

#pragma unroll
    for (int i = 0; i < 8; i++) {
        size_t cr = (size_t)(row0 + r0 + i) * N + col0 + c0;
#pragma unroll
        for (int j = 0; j < 8; j++) C[cr + j] = acc[i][j];
    }
}

// ---------------- LN over H=256 per row, fused e_src/e_dst GEMVs ----------------
// one warp per row; 8 warps per block
__global__ void __launch_bounds__(256)
ln_esrc_kernel(const float* __restrict__ pre, float* __restrict__ h,
               const float* __restrict__ lng, const float* __restrict__ lnb,
               const float* __restrict__ Watt,
               float* __restrict__ esrc, float* __restrict__ edst)
{
    int w = (blockIdx.x * blockDim.x + threadIdx.x) >> 5;   // 0 .. 4*16384-1
    int lane = threadIdx.x & 31;
    int hd = w >> 14;
    const float* row = pre + (size_t)w * 256;

    float x[8];
    float s = 0.f;
#pragma unroll
    for (int i = 0; i < 8; i++) { x[i] = row[lane + 32 * i]; s += x[i]; }
#pragma unroll
    for (int off = 16; off > 0; off >>= 1) s += __shfl_xor_sync(0xffffffffu, s, off);
    float mu = s * (1.f / 256.f);

    float v = 0.f;
#pragma unroll
    for (int i = 0; i < 8; i++) { float d = x[i] - mu; v += d * d; }
#pragma unroll
    for (int off = 16; off > 0; off >>= 1) v += __shfl_xor_sync(0xffffffffu, v, off);
    float rstd = rsqrtf(v * (1.f / 256.f) + 1e-5f);

    float es = 0.f, ed = 0.f;
    float* hrow = h + (size_t)w * 256;
#pragma unroll
    for (int i = 0; i < 8; i++) {
        int c = lane + 32 * i;
        float y = (x[i] - mu) * rstd * lng[hd * 256 + c] + lnb[hd * 256 + c];
        hrow[c] = y;
        es += y * Watt[hd * 512 + c];
        ed += y * Watt[hd * 512 + 256 + c];
    }
#pragma unroll
    for (int off = 16; off > 0; off >>= 1) {
        es += __shfl_xor_sync(0xffffffffu, es, off);
        ed += __shfl_xor_sync(0xffffffffu, ed, off);
    }
    if (lane == 0) { esrc[w] = es; edst[w] = ed; }
}

// ---------------- per-row: sigmoid, quantile(0.7) via bitonic sort, ----------------
// ---------------- masked leaky-relu softmax, sparse alpha@h gather  ----------------
__global__ void __launch_bounds__(256)
attn_kernel(const float* __restrict__ S, const float* __restrict__ h,
            const float* __restrict__ esrc, const float* __restrict__ edst,
            const float* __restrict__ batt, float* __restrict__ out)
{
    const int i = blockIdx.x, b = blockIdx.y, hd = blockIdx.z;
    const int tid = threadIdx.x;

    __shared__ float sA[1024];
    __shared__ float sSort[1024];   // reused for e / alpha after delta is computed
    __shared__ int   sList[1024];
    __shared__ int   sScan[256];
    __shared__ float sRed[256];
    __shared__ float sDelta;

    const size_t rowbase = ((size_t)(hd * 16 + b) * 1024 + i) * 1024;
    for (int j = tid; j < 1024; j += 256) {
        float v = S[rowbase + j];
        float a = 1.f / (1.f + expf(-v));
        sA[j] = a; sSort[j] = a;
    }

    // bitonic ascending sort of sSort[0..1023]
    for (int k = 2; k <= 1024; k <<= 1) {
        for (int j = k >> 1; j > 0; j >>= 1) {
            __syncthreads();
            for (int t = tid; t < 1024; t += 256) {
                int ixj = t ^ j;
                if (ixj > t) {
                    float a = sSort[t], c = sSort[ixj];
                    bool up = ((t & k) == 0);
                    if ((a > c) == up) { sSort[t] = c; sSort[ixj] = a; }
                }
            }
        }
    }
    __syncthreads();
    if (tid == 0) {
        float fr = 0.7f * 1023.0f - 716.0f;  // jnp 'linear' interpolation fraction
        sDelta = sSort[716] + fr * (sSort[717] - sSort[716]);
    }
    __syncthreads();
    const float delta = sDelta;

    // deterministic mask compaction (prefix-sum)
    int cnt = 0; int loc[4];
#pragma unroll
    for (int q = 0; q < 4; q++) {
        int j = tid * 4 + q;
        bool m = (sA[j] > delta) || (j == i);
        if (m) loc[cnt++] = j;
    }
    sScan[tid] = cnt;
    __syncthreads();
    for (int off = 1; off < 256; off <<= 1) {
        int v = (tid >= off) ? sScan[tid - off] : 0;
        __syncthreads();
        sScan[tid] += v;
        __syncthreads();
    }
    const int total = sScan[255];
    int base = sScan[tid] - cnt;
    for (int q = 0; q < cnt; q++) sList[base + q] = loc[q];
    __syncthreads();

    // e = leaky_relu(esrc_i + edst_j + batt) on masked set; softmax
    const int rowidx = hd * 16384 + b * 1024;
    const float ei = esrc[rowidx + i];
    const float bb = batt[hd];
    float lmax = -3.4e38f;
    for (int p = tid; p < total; p += 256) {
        int j = sList[p];
        float e = ei + edst[rowidx + j] + bb;
        e = (e >= 0.f) ? e : 0.01f * e;
        sSort[p] = e;
        lmax = fmaxf(lmax, e);
    }
    sRed[tid] = lmax; __syncthreads();
    for (int off = 128; off > 0; off >>= 1) {
        if (tid < off) sRed[tid] = fmaxf(sRed[tid], sRed[tid + off]);
        __syncthreads();
    }
    const float emax = sRed[0];
    __syncthreads();

    float lsum = 0.f;
    for (int p = tid; p < total; p += 256) {
        float a = expf(sSort[p] - emax);
        sSort[p] = a;
        lsum += a;
    }
    sRed[tid] = lsum; __syncthreads();
    for (int off = 128; off > 0; off >>= 1) {
        if (tid < off) sRed[tid] += sRed[tid + off];
        __syncthreads();
    }
    const float inv = 1.f / sRed[0];
    __syncthreads();

    // out_i[c] = sum over masked j of alpha_j * h[j][c]   (c = tid)
    const float* hbase = h + (size_t)rowidx * 256;
    float acc = 0.f;
    for (int p = 0; p < total; p++) {
        int j = sList[p];
        acc += sSort[p] * hbase[(size_t)j * 256 + tid];
    }
    out[((size_t)rowidx + i) * 256 + tid] = acc * inv;
}

// ---------------- mean over L per (head,batch) ----------------
__global__ void __launch_bounds__(256)
mean_kernel(const float* __restrict__ o, float* __restrict__ meanb)
{
    int z = blockIdx.x;        // hd*16+b
    int c = threadIdx.x;
    const float* p = o + (size_t)z * 1024 * 256 + c;
    float s = 0.f;
    for (int l = 0; l < 1024; l++) s += p[(size_t)l * 256];
    meanb[z * 256 + c] = s * (1.f / 1024.f);
}

// ---------------- final projections + LN; writes [ling|struct|concat] ----------------
__global__ void __launch_bounds__(256)
final_kernel(const float* __restrict__ meanb,
             const float* __restrict__ Wl, const float* __restrict__ bl,
             const float* __restrict__ Ws, const float* __restrict__ bs,
             const float* __restrict__ Wc, const float* __restrict__ bc,
             const float* __restrict__ gl, const float* __restrict__ betal,
             const float* __restrict__ gs, const float* __restrict__ betas,
             const float* __restrict__ gc, const float* __restrict__ betac,
             float* __restrict__ outp)
{
    const int b = blockIdx.x, type = blockIdx.y, tid = threadIdx.x;
    __shared__ float v[1024];
    __shared__ float red[256];

    const float *W, *bias, *g, *beta;
    int K, hbase;
    if (type == 0)      { W = Wl; bias = bl; g = gl; beta = betal; K = 512;  hbase = 0; }
    else if (type == 1) { W = Ws; bias = bs; g = gs; beta = betas; K = 512;  hbase = 2; }
    else                { W = Wc; bias = bc; g = gc; beta = betac; K = 1024; hbase = 0; }

    for (int k = tid; k < K; k += 256) {
        int head = hbase + (k >> 8);
        int c = k & 255;
        v[k] = meanb[(head * 16 + b) * 256 + c];
    }
    __syncthreads();

    float acc[3];
#pragma unroll
    for (int q = 0; q < 3; q++) {
        int c = tid + q * 256;
        float s = bias[c];
        for (int k = 0; k < K; k++) s += v[k] * W[(size_t)k * 768 + c];
        acc[q] = s;
    }

    red[tid] = acc[0] + acc[1] + acc[2];
    __syncthreads();
    for (int off = 128; off > 0; off >>= 1) {
        if (tid < off) red[tid] += red[tid + off];
        __syncthreads();
    }
    float mu = red[0] * (1.f / 768.f);
    __syncthreads();
    float d0 = acc[0] - mu, d1 = acc[1] - mu, d2 = acc[2] - mu;
    red[tid] = d0 * d0 + d1 * d1 + d2 * d2;
    __syncthreads();
    for (int off = 128; off > 0; off >>= 1) {
        if (tid < off) red[tid] += red[tid + off];
        __syncthreads();
    }
    float rstd = rsqrtf(red[0] * (1.f / 768.f) + 1e-5f);
    __syncthreads();

#pragma unroll
    for (int q = 0; q < 3; q++) {
        int c = tid + q * 256;
        outp[(size_t)type * 16 * 768 + (size_t)b * 768 + c] =
            (acc[q] - mu) * rstd * g[c] + beta[c];
    }
}

// ---------------- launch ----------------
extern "C" void kernel_launch(void* const* d_in, const int* in_sizes, int n_in,
                              void* d_out, int out_size)
{
    const float* x      = (const float*)d_in[0];   // (16,1024,768)
    const float* Wfc    = (const float*)d_in[1];   // (4,768,256)
    const float* bfc    = (const float*)d_in[2];   // (4,256)
    const float* lng    = (const float*)d_in[3];
    const float* lnb    = (const float*)d_in[4];
    const float* adjw   = (const float*)d_in[5];   // (4,256,256)
    const float* Watt   = (const float*)d_in[6];   // (4,512)
    const float* batt   = (const float*)d_in[7];   // (4,)
    const float* Wl     = (const float*)d_in[8];
    const float* bl     = (const float*)d_in[9];
    const float* Ws     = (const float*)d_in[10];
    const float* bs     = (const float*)d_in[11];
    const float* Wc     = (const float*)d_in[12];
    const float* bc     = (const float*)d_in[13];
    const float* gl     = (const float*)d_in[14];
    const float* betal  = (const float*)d_in[15];
    const float* gs     = (const float*)d_in[16];
    const float* betas  = (const float*)d_in[17];
    const float* gc     = (const float*)d_in[18];
    const float* betac  = (const float*)d_in[19];
    float* outp = (float*)d_out;

    float *h, *tmp, *S, *ob, *esrc, *edst, *meanb;
    cudaGetSymbolAddress((void**)&h,     g_h);
    cudaGetSymbolAddress((void**)&tmp,   g_tmp);
    cudaGetSymbolAddress((void**)&S,     g_S);
    cudaGetSymbolAddress((void**)&ob,    g_out);
    cudaGetSymbolAddress((void**)&esrc,  g_esrc);
    cudaGetSymbolAddress((void**)&edst,  g_edst);
    cudaGetSymbolAddress((void**)&meanb, g_mean);

    // K1: pre = x @ Wfc + bfc   (per head)
    sgemm_nn<<<dim3(2, 128, 4), 256>>>(x, Wfc, tmp, bfc,
                                       16384, 256, 768,
                                       (size_t)0, (size_t)768 * 256,
                                       (size_t)16384 * 256, (size_t)256);
    // K2: LN + e_src/e_dst
    ln_esrc_kernel<<<8192, 256>>>(tmp, h, lng, lnb, Watt, esrc, edst);
    // K3: g = h @ adjw (per head)
    sgemm_nn<<<dim3(2, 128, 4), 256>>>(h, adjw, tmp, nullptr,
                                       16384, 256, 256,
                                       (size_t)16384 * 256, (size_t)256 * 256,
                                       (size_t)16384 * 256, (size_t)0);
    // K4: S = g @ h^T per (head,batch): 64 batches of 1024x1024x256
    sgemm_nt<<<dim3(8, 8, 64), 256>>>(tmp, h, S,
                                      1024, 1024, 256,
                                      (size_t)1024 * 256, (size_t)1024 * 256,
                                      (size_t)1024 * 1024);
    // K5: quantile mask + masked softmax + sparse alpha@h
    attn_kernel<<<dim3(1024, 16, 4), 256>>>(S, h, esrc, edst, batt, ob);
    // K6: mean over L
    mean_kernel<<<64, 256>>>(ob, meanb);
    // K7: final projections + LN
    final_kernel<<<dim3(16, 3), 256>>>(meanb, Wl, bl, Ws, bs, Wc, bc,
                                       gl, betal, gs, betas, gc, betac, outp);
}

// round 3
// speedup vs baseline: 1.5471x; 1.5471x over previous
#include <cuda_runtime.h>
#include <cstdint>
#include <cstddef>

// ---------------- static scratch ----------------
//   g_h   [4][16384][256]  LN'd head features
//   g_tmp [4][16384][256]  pre-LN fc output, then reused for g = h@adjw
//   g_A   [4][16][1024][1024] sigmoid(S) attention probabilities
//   g_out [4][16384][256]  per-head attention output
__device__ float g_h[4 * 16384 * 256];
__device__ float g_tmp[4 * 16384 * 256];
__device__ float g_A[4 * 16 * 1024 * 1024];
__device__ float g_out[4 * 16384 * 256];
__device__ float g_esrc[4 * 16384];
__device__ float g_edst[4 * 16384];
__device__ float g_meanp[64 * 8 * 256];

// ---------------- 128x128x8 fp32 GEMM, C = A@B (+bias), double-buffered ----------------
__global__ void __launch_bounds__(256, 2)
sgemm_nn(const float* __restrict__ Ab, const float* __restrict__ Bb,
         float* __restrict__ Cb, const float* __restrict__ biasb,
         int M, int N, int K,
         size_t sA, size_t sB, size_t sC, size_t sBias)
{
    const float* A = Ab + (size_t)blockIdx.z * sA;
    const float* B = Bb + (size_t)blockIdx.z * sB;
    float* C = Cb + (size_t)blockIdx.z * sC;
    const float* bias = biasb ? biasb + (size_t)blockIdx.z * sBias : nullptr;

    __shared__ float As[2][8][128];
    __shared__ float Bs[2][8][128];

    const int tid = threadIdx.x;
    const int row0 = blockIdx.y * 128;
    const int col0 = blockIdx.x * 128;

    const int arow = tid >> 1;            // 0..127
    const int acol = (tid & 1) * 4;       // 0 or 4
    const int brow = tid >> 5;            // 0..7
    const int bcol = (tid & 31) * 4;      // 0..124

    const int ty = tid >> 4, tx = tid & 15;
    const int r0 = ty * 8, c0 = tx * 8;

    const float* Aptr = A + (size_t)(row0 + arow) * K + acol;
    const float* Bptr = B + (size_t)brow * N + col0 + bcol;

    float acc[8][8];
#pragma unroll
    for (int i = 0; i < 8; i++)
#pragma unroll
        for (int j = 0; j < 8; j++) acc[i][j] = 0.f;

    int buf = 0;
    {
        float4 av = *(const float4*)(Aptr);
        float4 bv = *(const float4*)(Bptr);
        As[0][acol + 0][arow] = av.x; As[0][acol + 1][arow] = av.y;
        As[0][acol + 2][arow] = av.z; As[0][acol + 3][arow] = av.w;
        *(float4*)&Bs[0][brow][bcol] = bv;
    }
    __syncthreads();

    const int nT = K >> 3;
    for (int t = 0; t < nT; ++t) {
        float4 av2, bv2;
        if (t + 1 < nT) {
            av2 = *(const float4*)(Aptr + (t + 1) * 8);
            bv2 = *(const float4*)(Bptr + (size_t)(t + 1) * 8 * N);
        }
#pragma unroll
        for (int kk = 0; kk < 8; kk++) {
            float a[8], b[8];
            *(float4*)(a)     = *(const float4*)&As[buf][kk][r0];
            *(float4*)(a + 4) = *(const float4*)&As[buf][kk][r0 + 4];
            *(float4*)(b)     = *(const float4*)&Bs[buf][kk][c0];
            *(float4*)(b + 4) = *(const float4*)&Bs[buf][kk][c0 + 4];
#pragma unroll
            for (int i = 0; i < 8; i++)
#pragma unroll
                for (int j = 0; j < 8; j++) acc[i][j] += a[i] * b[j];
        }
        if (t + 1 < nT) {
            buf ^= 1;
            As[buf][acol + 0][arow] = av2.x; As[buf][acol + 1][arow] = av2.y;
            As[buf][acol + 2][arow] = av2.z; As[buf][acol + 3][arow] = av2.w;
            *(float4*)&Bs[buf][brow][bcol] = bv2;
            __syncthreads();
        }
    }

#pragma unroll
    for (int i = 0; i < 8; i++) {
        size_t cr = (size_t)(row0 + r0 + i) * N + col0 + c0;
#pragma unroll
        for (int j = 0; j < 8; j++) {
            float v = acc[i][j];
            if (bias) v += bias[col0 + c0 + j];
            C[cr + j] = v;
        }
    }
}

// ---------------- C = sigmoid(A @ B^T), double-buffered ----------------
__global__ void __launch_bounds__(256, 2)
sgemm_nt_sig(const float* __restrict__ Ab, const float* __restrict__ Bb,
             float* __restrict__ Cb,
             int M, int N, int K,
             size_t sA, size_t sB, size_t sC)
{
    const float* A = Ab + (size_t)blockIdx.z * sA;
    const float* B = Bb + (size_t)blockIdx.z * sB;
    float* C = Cb + (size_t)blockIdx.z * sC;

    __shared__ float As[2][8][128];
    __shared__ float Bs[2][8][128];

    const int tid = threadIdx.x;
    const int row0 = blockIdx.y * 128;
    const int col0 = blockIdx.x * 128;

    const int arow = tid >> 1;
    const int acol = (tid & 1) * 4;

    const int ty = tid >> 4, tx = tid & 15;
    const int r0 = ty * 8, c0 = tx * 8;

    const float* Aptr = A + (size_t)(row0 + arow) * K + acol;
    const float* Bptr = B + (size_t)(col0 + arow) * K + acol;

    float acc[8][8];
#pragma unroll
    for (int i = 0; i < 8; i++)
#pragma unroll
        for (int j = 0; j < 8; j++) acc[i][j] = 0.f;

    int buf = 0;
    {
        float4 av = *(const float4*)(Aptr);
        float4 bv = *(const float4*)(Bptr);
        As[0][acol + 0][arow] = av.x; As[0][acol + 1][arow] = av.y;
        As[0][acol + 2][arow] = av.z; As[0][acol + 3][arow] = av.w;
        Bs[0][acol + 0][arow] = bv.x; Bs[0][acol + 1][arow] = bv.y;
        Bs[0][acol + 2][arow] = bv.z; Bs[0][acol + 3][arow] = bv.w;
    }
    __syncthreads();

    const int nT = K >> 3;
    for (int t = 0; t < nT; ++t) {
        float4 av2, bv2;
        if (t + 1 < nT) {
            av2 = *(const float4*)(Aptr + (t + 1) * 8);
            bv2 = *(const float4*)(Bptr + (t + 1) * 8);
        }
#pragma unroll
        for (int kk = 0; kk < 8; kk++) {
            float a[8], b[8];
            *(float4*)(a)     = *(const float4*)&As[buf][kk][r0];
            *(float4*)(a + 4) = *(const float4*)&As[buf][kk][r0 + 4];
            *(float4*)(b)     = *(const float4*)&Bs[buf][kk][c0];
            *(float4*)(b + 4) = *(const float4*)&Bs[buf][kk][c0 + 4];
#pragma unroll
            for (int i = 0; i < 8; i++)
#pragma unroll
                for (int j = 0; j < 8; j++) acc[i][j] += a[i] * b[j];
        }
        if (t + 1 < nT) {
            buf ^= 1;
            As[buf][acol + 0][arow] = av2.x; As[buf][acol + 1][arow] = av2.y;
            As[buf][acol + 2][arow] = av2.z; As[buf][acol + 3][arow] = av2.w;
            Bs[buf][acol + 0][arow] = bv2.x; Bs[buf][acol + 1][arow] = bv2.y;
            Bs[buf][acol + 2][arow] = bv2.z; Bs[buf][acol + 3][arow] = bv2.w;
            __syncthreads();
        }
    }

#pragma unroll
    for (int i = 0; i < 8; i++) {
        size_t cr = (size_t)(row0 + r0 + i) * N + col0 + c0;
#pragma unroll
        for (int j = 0; j < 8; j++)
            C[cr + j] = 1.f / (1.f + expf(-acc[i][j]));
    }
}

// ---------------- LN over H=256 per row, fused e_src/e_dst GEMVs ----------------
__global__ void __launch_bounds__(256)
ln_esrc_kernel(const float* __restrict__ pre, float* __restrict__ h,
               const float* __restrict__ lng, const float* __restrict__ lnb,
               const float* __restrict__ Watt,
               float* __restrict__ esrc, float* __restrict__ edst)
{
    int w = (blockIdx.x * blockDim.x + threadIdx.x) >> 5;
    int lane = threadIdx.x & 31;
    int hd = w >> 14;
    const float* row = pre + (size_t)w * 256;

    float x[8];
    float s = 0.f;
#pragma unroll
    for (int i = 0; i < 8; i++) { x[i] = row[lane + 32 * i]; s += x[i]; }
#pragma unroll
    for (int off = 16; off > 0; off >>= 1) s += __shfl_xor_sync(0xffffffffu, s, off);
    float mu = s * (1.f / 256.f);

    float v = 0.f;
#pragma unroll
    for (int i = 0; i < 8; i++) { float d = x[i] - mu; v += d * d; }
#pragma unroll
    for (int off = 16; off > 0; off >>= 1) v += __shfl_xor_sync(0xffffffffu, v, off);
    float rstd = rsqrtf(v * (1.f / 256.f) + 1e-5f);

    float es = 0.f, ed = 0.f;
    float* hrow = h + (size_t)w * 256;
#pragma unroll
    for (int i = 0; i < 8; i++) {
        int c = lane + 32 * i;
        float y = (x[i] - mu) * rstd * lng[hd * 256 + c] + lnb[hd * 256 + c];
        hrow[c] = y;
        es += y * Watt[hd * 512 + c];
        ed += y * Watt[hd * 512 + 256 + c];
    }
#pragma unroll
    for (int off = 16; off > 0; off >>= 1) {
        es += __shfl_xor_sync(0xffffffffu, es, off);
        ed += __shfl_xor_sync(0xffffffffu, ed, off);
    }
    if (lane == 0) { esrc[w] = es; edst[w] = ed; }
}

// ---------------- per-row: radix-select quantile, masked softmax, sparse gather ----------------
__global__ void __launch_bounds__(256)
attn_kernel(const float* __restrict__ Aprob, const float* __restrict__ h,
            const float* __restrict__ esrc, const float* __restrict__ edst,
            const float* __restrict__ batt, float* __restrict__ out)
{
    const int i = blockIdx.x, b = blockIdx.y, hd = blockIdx.z;
    const int tid = threadIdx.x;

    __shared__ float sA[1024];
    __shared__ float sE[1024];
    __shared__ int   sList[1024];
    __shared__ unsigned int sHist[256];
    __shared__ int   sScan[256];
    __shared__ float sRed[256];
    __shared__ int   sSel, sRank;

    const size_t rowbase = ((size_t)(hd * 16 + b) * 1024 + i) * 1024;
#pragma unroll
    for (int q = 0; q < 4; q++)
        sA[tid + 256 * q] = Aprob[rowbase + tid + 256 * q];
    __syncthreads();

    // ---- radix select: exact value at ascending rank 716 (keys in [0,1] -> uint monotonic)
    int rank = 716;
    unsigned int prefval = 0u, maskhi = 0u;
    for (int shift = 24; shift >= 0; shift -= 8) {
        sHist[tid] = 0u;
        __syncthreads();
#pragma unroll
        for (int q = 0; q < 4; q++) {
            unsigned int k = __float_as_uint(sA[tid + 256 * q]);
            if ((k & maskhi) == prefval)
                atomicAdd(&sHist[(k >> shift) & 255u], 1u);
        }
        __syncthreads();
        for (int off = 1; off < 256; off <<= 1) {
            unsigned int v = (tid >= off) ? sHist[tid - off] : 0u;
            __syncthreads();
            sHist[tid] += v;
            __syncthreads();
        }
        int cum  = (int)sHist[tid];
        int prev = (tid > 0) ? (int)sHist[tid - 1] : 0;
        if (rank >= prev && rank < cum) { sSel = tid; sRank = rank - prev; }
        __syncthreads();
        prefval |= ((unsigned int)sSel) << shift;
        maskhi  |= 0xFFu << shift;
        rank = sRank;
        __syncthreads();
    }
    const float v716 = __uint_as_float(prefval);

    // ---- value at rank 717: count <= v716, min above
    int cLE = 0; unsigned int mA = 0xFFFFFFFFu;
#pragma unroll
    for (int q = 0; q < 4; q++) {
        float a = sA[tid + 256 * q];
        if (a <= v716) cLE++;
        else { unsigned int k = __float_as_uint(a); mA = (k < mA) ? k : mA; }
    }
    sScan[tid] = cLE; sHist[tid] = mA;
    __syncthreads();
    for (int off = 128; off > 0; off >>= 1) {
        if (tid < off) {
            sScan[tid] += sScan[tid + off];
            unsigned int o = sHist[tid + off];
            if (o < sHist[tid]) sHist[tid] = o;
        }
        __syncthreads();
    }
    const float v717 = (sScan[0] > 717) ? v716 : __uint_as_float(sHist[0]);
    __syncthreads();

    const float fr = 0.7f * 1023.0f - 716.0f;   // jnp float32 'linear' interp fraction
    const float delta = v716 + fr * (v717 - v716);

    // ---- mask compaction (deterministic prefix-sum)
    int cnt = 0; int loc[4];
#pragma unroll
    for (int q = 0; q < 4; q++) {
        int j = tid * 4 + q;
        bool m = (sA[j] > delta) || (j == i);
        if (m) loc[cnt++] = j;
    }
    sScan[tid] = cnt;
    __syncthreads();
    for (int off = 1; off < 256; off <<= 1) {
        int v = (tid >= off) ? sScan[tid - off] : 0;
        __syncthreads();
        sScan[tid] += v;
        __syncthreads();
    }
    const int total = sScan[255];
    int base = sScan[tid] - cnt;
    for (int q = 0; q < cnt; q++) sList[base + q] = loc[q];
    __syncthreads();

    // ---- masked leaky-relu softmax
    const int rowidx = hd * 16384 + b * 1024;
    const float ei = esrc[rowidx + i];
    const float bb = batt[hd];
    float lmax = -3.4e38f;
    for (int p = tid; p < total; p += 256) {
        int j = sList[p];
        float e = ei + edst[rowidx + j] + bb;
        e = (e >= 0.f) ? e : 0.01f * e;
        sE[p] = e;
        lmax = fmaxf(lmax, e);
    }
    sRed[tid] = lmax; __syncthreads();
    for (int off = 128; off > 0; off >>= 1) {
        if (tid < off) sRed[tid] = fmaxf(sRed[tid], sRed[tid + off]);
        __syncthreads();
    }
    const float emax = sRed[0];
    __syncthreads();

    float lsum = 0.f;
    for (int p = tid; p < total; p += 256) {
        float a = expf(sE[p] - emax);
        sE[p] = a;
        lsum += a;
    }
    sRed[tid] = lsum; __syncthreads();
    for (int off = 128; off > 0; off >>= 1) {
        if (tid < off) sRed[tid] += sRed[tid + off];
        __syncthreads();
    }
    const float inv = 1.f / sRed[0];
    __syncthreads();

    // ---- out_i[c] = sum over masked j of alpha_j * h[j][c]
    const float* hbase = h + (size_t)rowidx * 256;
    float acc = 0.f;
    for (int p = 0; p < total; p++) {
        int j = sList[p];
        acc += sE[p] * hbase[(size_t)j * 256 + tid];
    }
    out[((size_t)rowidx + i) * 256 + tid] = acc * inv;
}

// ---------------- partial mean over L per (head,batch): 8 chunks of 128 ----------------
__global__ void __launch_bounds__(256)
mean_kernel(const float* __restrict__ o, float* __restrict__ meanp)
{
    int z = blockIdx.x;        // hd*16+b
    int ch = blockIdx.y;       // chunk 0..7
    int c = threadIdx.x;
    const float* p = o + (size_t)z * 262144 + (size_t)ch * 128 * 256 + c;
    float s = 0.f;
    for (int l = 0; l < 128; l++) s += p[(size_t)l * 256];
    meanp[(z * 8 + ch) * 256 + c] = s;
}

// ---------------- final projections + LN; writes [ling|struct|concat] ----------------
__global__ void __launch_bounds__(256)
final_kernel(const float* __restrict__ meanp,
             const float* __restrict__ Wl, const float* __restrict__ bl,
             const float* __restrict__ Ws, const float* __restrict__ bs,
             const float* __restrict__ Wc, const float* __restrict__ bc,
             const float* __restrict__ gl, const float* __restrict__ betal,
             const float* __restrict__ gs, const float* __restrict__ betas,
             const float* __restrict__ gc, const float* __restrict__ betac,
             float* __restrict__ outp)
{
    const int b = blockIdx.x, type = blockIdx.y, tid = threadIdx.x;
    __shared__ float v[1024];
    __shared__ float red[256];

    const float *W, *bias, *g, *beta;
    int K, hbase;
    if (type == 0)      { W = Wl; bias = bl; g = gl; beta = betal; K = 512;  hbase = 0; }
    else if (type == 1) { W = Ws; bias = bs; g = gs; beta = betas; K = 512;  hbase = 2; }
    else                { W = Wc; bias = bc; g = gc; beta = betac; K = 1024; hbase = 0; }

    for (int k = tid; k < K; k += 256) {
        int head = hbase + (k >> 8);
        int c = k & 255;
        float s = 0.f;
#pragma unroll
        for (int c8 = 0; c8 < 8; c8++)
            s += meanp[((head * 16 + b) * 8 + c8) * 256 + c];
        v[k] = s * (1.f / 1024.f);
    }
    __syncthreads();

    float acc[3];
#pragma unroll
    for (int q = 0; q < 3; q++) {
        int c = tid + q * 256;
        float s = bias[c];
        for (int k = 0; k < K; k++) s += v[k] * W[(size_t)k * 768 + c];
        acc[q] = s;
    }

    red[tid] = acc[0] + acc[1] + acc[2];
    __syncthreads();
    for (int off = 128; off > 0; off >>= 1) {
        if (tid < off) red[tid] += red[tid + off];
        __syncthreads();
    }
    float mu = red[0] * (1.f / 768.f);
    __syncthreads();
    float d0 = acc[0] - mu, d1 = acc[1] - mu, d2 = acc[2] - mu;
    red[tid] = d0 * d0 + d1 * d1 + d2 * d2;
    __syncthreads();
    for (int off = 128; off > 0; off >>= 1) {
        if (tid < off) red[tid] += red[tid + off];
        __syncthreads();
    }
    float rstd = rsqrtf(red[0] * (1.f / 768.f) + 1e-5f);
    __syncthreads();

#pragma unroll
    for (int q = 0; q < 3; q++) {
        int c = tid + q * 256;
        outp[(size_t)type * 16 * 768 + (size_t)b * 768 + c] =
            (acc[q] - mu) * rstd * g[c] + beta[c];
    }
}

// ---------------- launch ----------------
extern "C" void kernel_launch(void* const* d_in, const int* in_sizes, int n_in,
                              void* d_out, int out_size)
{
    const float* x      = (const float*)d_in[0];
    const float* Wfc    = (const float*)d_in[1];
    const float* bfc    = (const float*)d_in[2];
    const float* lng    = (const float*)d_in[3];
    const float* lnb    = (const float*)d_in[4];
    const float* adjw   = (const float*)d_in[5];
    const float* Watt   = (const float*)d_in[6];
    const float* batt   = (const float*)d_in[7];
    const float* Wl     = (const float*)d_in[8];
    const float* bl     = (const float*)d_in[9];
    const float* Ws     = (const float*)d_in[10];
    const float* bs     = (const float*)d_in[11];
    const float* Wc     = (const float*)d_in[12];
    const float* bc     = (const float*)d_in[13];
    const float* gl     = (const float*)d_in[14];
    const float* betal  = (const float*)d_in[15];
    const float* gs     = (const float*)d_in[16];
    const float* betas  = (const float*)d_in[17];
    const float* gc     = (const float*)d_in[18];
    const float* betac  = (const float*)d_in[19];
    float* outp = (float*)d_out;

    float *h, *tmp, *A, *ob, *esrc, *edst, *meanp;
    cudaGetSymbolAddress((void**)&h,     g_h);
    cudaGetSymbolAddress((void**)&tmp,   g_tmp);
    cudaGetSymbolAddress((void**)&A,     g_A);
    cudaGetSymbolAddress((void**)&ob,    g_out);
    cudaGetSymbolAddress((void**)&esrc,  g_esrc);
    cudaGetSymbolAddress((void**)&edst,  g_edst);
    cudaGetSymbolAddress((void**)&meanp, g_meanp);

    // K1: pre = x @ Wfc + bfc   (per head)
    sgemm_nn<<<dim3(2, 128, 4), 256>>>(x, Wfc, tmp, bfc,
                                       16384, 256, 768,
                                       (size_t)0, (size_t)768 * 256,
                                       (size_t)16384 * 256, (size_t)256);
    // K2: LN + e_src/e_dst
    ln_esrc_kernel<<<8192, 256>>>(tmp, h, lng, lnb, Watt, esrc, edst);
    // K3: g = h @ adjw (per head)
    sgemm_nn<<<dim3(2, 128, 4), 256>>>(h, adjw, tmp, nullptr,
                                       16384, 256, 256,
                                       (size_t)16384 * 256, (size_t)256 * 256,
                                       (size_t)16384 * 256, (size_t)0);
    // K4: A = sigmoid(g @ h^T) per (head,batch)
    sgemm_nt_sig<<<dim3(8, 8, 64), 256>>>(tmp, h, A,
                                          1024, 1024, 256,
                                          (size_t)1024 * 256, (size_t)1024 * 256,
                                          (size_t)1024 * 1024);
    // K5: radix-select quantile + masked softmax + sparse alpha@h
    attn_kernel<<<dim3(1024, 16, 4), 256>>>(A, h, esrc, edst, batt, ob);
    // K6: partial mean over L
    mean_kernel<<<dim3(64, 8), 256>>>(ob, meanp);
    // K7: final projections + LN
    final_kernel<<<dim3(16, 3), 256>>>(meanp, Wl, bl, Ws, bs, Wc, bc,
                                       gl, betal, gs, betas, gc, betac, outp);
}